// round 2
// baseline (speedup 1.0000x reference)
#include <cuda_runtime.h>
#include <cstdint>

// Problem constants (shapes fixed by the dataset).
#define NMAX   100000
#define EMAX   800000
#define F1     128      // input features
#define HID    256      // hidden
#define NCLS   40       // classes
#define NPAD   64       // padded classes for GEMM2

// ---------------- scratch (device globals; no allocation allowed) ----------
__device__ float g_dinv[NMAX];
__device__ int   g_cnt[NMAX];
__device__ int   g_rows[NMAX];      // inclusive scan -> exclusive row starts
__device__ int   g_cursor[NMAX];
__device__ int   g_csrc[EMAX];      // CSR: src node per (dst-bucketed) edge
__device__ int   g_bsum[128];
__device__ float g_agg1[(size_t)NMAX * F1];   // 51.2 MB
__device__ float g_h1  [(size_t)NMAX * HID];  // 102.4 MB
__device__ float g_l2h [(size_t)NMAX * NPAD]; // 25.6 MB
__device__ float g_w2p [HID * NPAD];          // padded W2

// ---------------- degree / CSR build ---------------------------------------
__global__ void k_zero_cnt(int n) {
    int i = blockIdx.x * blockDim.x + threadIdx.x;
    if (i < n) g_cnt[i] = 0;
}

__global__ void k_count(const int* __restrict__ dst, int E) {
    int e = blockIdx.x * blockDim.x + threadIdx.x;
    if (e < E) atomicAdd(&g_cnt[dst[e]], 1);
}

__global__ void k_dinv(int n) {
    int i = blockIdx.x * blockDim.x + threadIdx.x;
    if (i < n) g_dinv[i] = rsqrtf((float)(g_cnt[i] + 1));  // +1 self loop
}

// block-wise inclusive scan (1024/block)
__global__ void k_scan1(int n) {
    __shared__ int s[1024];
    int t = threadIdx.x;
    int i = blockIdx.x * 1024 + t;
    int v = (i < n) ? g_cnt[i] : 0;
    s[t] = v;
    __syncthreads();
    #pragma unroll
    for (int off = 1; off < 1024; off <<= 1) {
        int add = (t >= off) ? s[t - off] : 0;
        __syncthreads();
        s[t] += add;
        __syncthreads();
    }
    if (i < n) g_rows[i] = s[t];                    // inclusive
    if (t == 1023) g_bsum[blockIdx.x] = s[1023];    // block total
}

// scan of block sums (<=128 blocks), result exclusive
__global__ void k_scan2(int nb) {
    __shared__ int s[128];
    int t = threadIdx.x;
    int v = (t < nb) ? g_bsum[t] : 0;
    s[t] = v;
    __syncthreads();
    #pragma unroll
    for (int off = 1; off < 128; off <<= 1) {
        int add = (t >= off) ? s[t - off] : 0;
        __syncthreads();
        s[t] += add;
        __syncthreads();
    }
    if (t < nb) g_bsum[t] = s[t] - v;   // exclusive
}

__global__ void k_scan3(int n) {
    int i = blockIdx.x * blockDim.x + threadIdx.x;
    if (i < n) {
        int excl = g_rows[i] - g_cnt[i] + g_bsum[i >> 10];
        g_rows[i]   = excl;
        g_cursor[i] = excl;
    }
}

__global__ void k_fill(const int* __restrict__ src, const int* __restrict__ dst, int E) {
    int e = blockIdx.x * blockDim.x + threadIdx.x;
    if (e < E) {
        int d = dst[e];
        int pos = atomicAdd(&g_cursor[d], 1);
        g_csrc[pos] = src[e];
    }
}

// ---------------- layer-1 aggregation: agg1 = Â x (128 feats) --------------
// one warp per node; lane holds a float4 chunk (32*4 = 128 feats)
__global__ void k_agg1(const float* __restrict__ x, int n) {
    int node = (blockIdx.x * blockDim.x + threadIdx.x) >> 5;
    int lane = threadIdx.x & 31;
    if (node >= n) return;
    int beg = g_rows[node];
    int cnt = g_cnt[node];
    float4 acc = make_float4(0.f, 0.f, 0.f, 0.f);
    for (int i = 0; i < cnt; i++) {
        int s = g_csrc[beg + i];
        float ws = g_dinv[s];
        float4 v = ((const float4*)x)[(size_t)s * 32 + lane];
        acc.x += ws * v.x; acc.y += ws * v.y; acc.z += ws * v.z; acc.w += ws * v.w;
    }
    float wd = g_dinv[node];
    float4 xv = ((const float4*)x)[(size_t)node * 32 + lane];
    float4 o;
    o.x = wd * (acc.x + wd * xv.x);
    o.y = wd * (acc.y + wd * xv.y);
    o.z = wd * (acc.z + wd * xv.z);
    o.w = wd * (acc.w + wd * xv.w);
    ((float4*)g_agg1)[(size_t)node * 32 + lane] = o;
}

// ---------------- fp32 tiled GEMM: C = A(MxK) * B(KxN) ---------------------
// BM=128, BN=64, BK=16, 256 threads, 8x4 microtile.
// MODE 1: C = relu(C + bias)   MODE 0: plain
template <int MODE>
__global__ void __launch_bounds__(256)
k_gemm(const float* __restrict__ A, const float* __restrict__ B,
       const float* __restrict__ bias, float* __restrict__ C,
       int M, int N, int K)
{
    __shared__ float sA[16][128];
    __shared__ float sB[16][64];
    int t  = threadIdx.x;
    int tx = t & 15;          // col group 0..15 (4 cols each)
    int ty = t >> 4;          // row group 0..15 (8 rows each)
    int m0 = blockIdx.y * 128;
    int n0 = blockIdx.x * 64;

    int arow = t & 127;           // A-load row within tile
    int akc  = (t >> 7) * 8;      // A-load k chunk (0 or 8)
    int bkb  = t >> 4;            // B-load k row 0..15
    int bcol = (t & 15) * 4;      // B-load col

    float acc[8][4];
    #pragma unroll
    for (int i = 0; i < 8; i++)
        #pragma unroll
        for (int j = 0; j < 4; j++) acc[i][j] = 0.f;

    bool arow_ok = (m0 + arow) < M;
    const float* Ap = A + (size_t)(m0 + arow) * K + akc;

    for (int k0 = 0; k0 < K; k0 += 16) {
        float4 a0 = make_float4(0.f, 0.f, 0.f, 0.f), a1 = a0;
        if (arow_ok) {
            a0 = *(const float4*)(Ap + k0);
            a1 = *(const float4*)(Ap + k0 + 4);
        }
        float4 b0 = *(const float4*)(B + (size_t)(k0 + bkb) * N + n0 + bcol);
        __syncthreads();
        sA[akc + 0][arow] = a0.x; sA[akc + 1][arow] = a0.y;
        sA[akc + 2][arow] = a0.z; sA[akc + 3][arow] = a0.w;
        sA[akc + 4][arow] = a1.x; sA[akc + 5][arow] = a1.y;
        sA[akc + 6][arow] = a1.z; sA[akc + 7][arow] = a1.w;
        *(float4*)&sB[bkb][bcol] = b0;
        __syncthreads();
        #pragma unroll
        for (int k = 0; k < 16; k++) {
            float ar[8], br[4];
            *(float4*)&ar[0] = *(const float4*)&sA[k][ty * 8];
            *(float4*)&ar[4] = *(const float4*)&sA[k][ty * 8 + 4];
            *(float4*)&br[0] = *(const float4*)&sB[k][tx * 4];
            #pragma unroll
            for (int i = 0; i < 8; i++)
                #pragma unroll
                for (int j = 0; j < 4; j++)
                    acc[i][j] += ar[i] * br[j];
        }
    }

    #pragma unroll
    for (int i = 0; i < 8; i++) {
        int r = m0 + ty * 8 + i;
        if (r < M) {
            float4 o;
            float* op = (float*)&o;
            #pragma unroll
            for (int j = 0; j < 4; j++) {
                float v = acc[i][j];
                if (MODE == 1) { v += bias[n0 + tx * 4 + j]; v = fmaxf(v, 0.f); }
                op[j] = v;
            }
            *(float4*)(C + (size_t)r * N + n0 + tx * 4) = o;
        }
    }
}

// ---------------- pad W2 (256x40 -> 256x64, zero fill) ---------------------
__global__ void k_padw2(const float* __restrict__ W2) {
    int t = blockIdx.x * blockDim.x + threadIdx.x;
    if (t < HID * NPAD) {
        int k = t / NPAD, c = t % NPAD;
        g_w2p[t] = (c < NCLS) ? W2[k * NCLS + c] : 0.f;
    }
}

// ---------------- layer-2 aggregation + bias + log_softmax -----------------
// one warp per node; lane holds class `lane`, lanes<8 also hold class 32+lane
__global__ void k_agg2_softmax(const float* __restrict__ b2,
                               float* __restrict__ out, int n) {
    int node = (blockIdx.x * blockDim.x + threadIdx.x) >> 5;
    int lane = threadIdx.x & 31;
    if (node >= n) return;
    int beg = g_rows[node];
    int cnt = g_cnt[node];
    float a0 = 0.f, a1 = 0.f;
    for (int i = 0; i < cnt; i++) {
        int s = g_csrc[beg + i];
        float ws = g_dinv[s];
        const float* row = g_l2h + (size_t)s * NPAD;
        a0 += ws * row[lane];
        if (lane < 8) a1 += ws * row[32 + lane];
    }
    float wd = g_dinv[node];
    const float* srow = g_l2h + (size_t)node * NPAD;
    float v0 = b2[lane] + wd * (a0 + wd * srow[lane]);
    float v1 = -1e30f;
    if (lane < 8) v1 = b2[32 + lane] + wd * (a1 + wd * srow[32 + lane]);

    // warp-wide max
    float m = fmaxf(v0, v1);
    #pragma unroll
    for (int off = 16; off; off >>= 1)
        m = fmaxf(m, __shfl_xor_sync(0xffffffffu, m, off));
    // warp-wide sum of exp
    float e = expf(v0 - m) + ((lane < 8) ? expf(v1 - m) : 0.f);
    #pragma unroll
    for (int off = 16; off; off >>= 1)
        e += __shfl_xor_sync(0xffffffffu, e, off);
    float lse = m + logf(e);

    out[(size_t)node * NCLS + lane] = v0 - lse;
    if (lane < 8) out[(size_t)node * NCLS + 32 + lane] = v1 - lse;
}

// ---------------- host ------------------------------------------------------
extern "C" void kernel_launch(void* const* d_in, const int* in_sizes, int n_in,
                              void* d_out, int out_size) {
    const float* x  = (const float*)d_in[0];
    const int*   ei = (const int*)d_in[1];
    const float* W1 = (const float*)d_in[2];
    const float* b1 = (const float*)d_in[3];
    const float* W2 = (const float*)d_in[4];
    const float* b2 = (const float*)d_in[5];
    float* out = (float*)d_out;

    int N = in_sizes[0] / F1;
    int E = in_sizes[1] / 2;
    const int* src = ei;
    const int* dst = ei + E;

    float *p_agg1, *p_h1, *p_l2h, *p_w2p;
    cudaGetSymbolAddress((void**)&p_agg1, g_agg1);
    cudaGetSymbolAddress((void**)&p_h1,   g_h1);
    cudaGetSymbolAddress((void**)&p_l2h,  g_l2h);
    cudaGetSymbolAddress((void**)&p_w2p,  g_w2p);

    int nb = (N + 1023) / 1024;

    k_zero_cnt<<<(N + 255) / 256, 256>>>(N);
    k_count  <<<(E + 255) / 256, 256>>>(dst, E);
    k_dinv   <<<(N + 255) / 256, 256>>>(N);
    k_scan1  <<<nb, 1024>>>(N);
    k_scan2  <<<1, 128>>>(nb);
    k_scan3  <<<(N + 255) / 256, 256>>>(N);
    k_fill   <<<(E + 255) / 256, 256>>>(src, dst, E);

    // layer 1: aggregate(x) -> GEMM(+bias, relu)
    k_agg1<<<((size_t)N * 32 + 255) / 256, 256>>>(x, N);
    {
        dim3 grid(HID / 64, (N + 127) / 128);
        k_gemm<1><<<grid, 256>>>(p_agg1, W1, b1, p_h1, N, HID, F1);
    }

    // layer 2: GEMM (padded 40->64) -> aggregate + bias + log_softmax
    k_padw2<<<(HID * NPAD + 255) / 256, 256>>>(W2);
    {
        dim3 grid(NPAD / 64, (N + 127) / 128);
        k_gemm<0><<<grid, 256>>>(p_h1, p_w2p, nullptr, p_l2h, N, NPAD, HID);
    }
    k_agg2_softmax<<<((size_t)N * 32 + 255) / 256, 256>>>(b2, out, N);
}

// round 8
// speedup vs baseline: 1.5012x; 1.5012x over previous
#include <cuda_runtime.h>
#include <cstdint>

// Problem constants (shapes fixed by the dataset).
#define NMAX   100000
#define EMAX   800000
#define F1     128      // input features
#define HID    256      // hidden
#define NCLS   40       // classes
#define NPAD   64       // padded classes for GEMM2

// ---------------- scratch (device globals; no allocation allowed) ----------
__device__ float g_dinv[NMAX];
__device__ int   g_cnt[NMAX];
__device__ int   g_rows[NMAX];
__device__ int   g_cursor[NMAX];
__device__ int   g_csrc[EMAX];
__device__ int   g_bsum[128];
__device__ float g_agg1[(size_t)NMAX * F1];   // 51.2 MB (tf32-rounded)
__device__ float g_h1  [(size_t)NMAX * HID];  // 102.4 MB (tf32-rounded)
__device__ float g_l2h [(size_t)NMAX * NPAD]; // 25.6 MB
__device__ float g_w1t [HID * F1];            // W1^T  [256][128] tf32
__device__ float g_w2t [NPAD * HID];          // W2^T padded [64][256] tf32

// ---------------- small helpers --------------------------------------------
__device__ __forceinline__ float tf32r(float x) {
    uint32_t u;
    asm("cvt.rna.tf32.f32 %0, %1;" : "=r"(u) : "f"(x));
    return __uint_as_float(u);
}

// ---------------- degree / CSR build ---------------------------------------
__global__ void k_zero_cnt(int n) {
    int i = blockIdx.x * blockDim.x + threadIdx.x;
    if (i < n) g_cnt[i] = 0;
}

__global__ void k_count(const int* __restrict__ dst, int E) {
    int e = blockIdx.x * blockDim.x + threadIdx.x;
    if (e < E) atomicAdd(&g_cnt[dst[e]], 1);
}

__global__ void k_dinv(int n) {
    int i = blockIdx.x * blockDim.x + threadIdx.x;
    if (i < n) g_dinv[i] = rsqrtf((float)(g_cnt[i] + 1));
}

__global__ void k_scan1(int n) {
    __shared__ int s[1024];
    int t = threadIdx.x;
    int i = blockIdx.x * 1024 + t;
    int v = (i < n) ? g_cnt[i] : 0;
    s[t] = v;
    __syncthreads();
    #pragma unroll
    for (int off = 1; off < 1024; off <<= 1) {
        int add = (t >= off) ? s[t - off] : 0;
        __syncthreads();
        s[t] += add;
        __syncthreads();
    }
    if (i < n) g_rows[i] = s[t];
    if (t == 1023) g_bsum[blockIdx.x] = s[1023];
}

__global__ void k_scan2(int nb) {
    __shared__ int s[128];
    int t = threadIdx.x;
    int v = (t < nb) ? g_bsum[t] : 0;
    s[t] = v;
    __syncthreads();
    #pragma unroll
    for (int off = 1; off < 128; off <<= 1) {
        int add = (t >= off) ? s[t - off] : 0;
        __syncthreads();
        s[t] += add;
        __syncthreads();
    }
    if (t < nb) g_bsum[t] = s[t] - v;
}

__global__ void k_scan3(int n) {
    int i = blockIdx.x * blockDim.x + threadIdx.x;
    if (i < n) {
        int excl = g_rows[i] - g_cnt[i] + g_bsum[i >> 10];
        g_rows[i]   = excl;
        g_cursor[i] = excl;
    }
}

__global__ void k_fill(const int* __restrict__ src, const int* __restrict__ dst, int E) {
    int e = blockIdx.x * blockDim.x + threadIdx.x;
    if (e < E) {
        int d = dst[e];
        int pos = atomicAdd(&g_cursor[d], 1);
        g_csrc[pos] = src[e];
    }
}

// ---------------- weight transpose + tf32 rounding --------------------------
__global__ void k_w1t(const float* __restrict__ W1) {   // W1 [128][256]
    int t = blockIdx.x * blockDim.x + threadIdx.x;
    if (t < HID * F1) {
        int n = t / F1, k = t % F1;
        g_w1t[t] = tf32r(W1[k * HID + n]);
    }
}

__global__ void k_w2t(const float* __restrict__ W2) {   // W2 [256][40]
    int t = blockIdx.x * blockDim.x + threadIdx.x;
    if (t < NPAD * HID) {
        int n = t / HID, k = t % HID;
        g_w2t[t] = (n < NCLS) ? tf32r(W2[k * NCLS + n]) : 0.f;
    }
}

// ---------------- layer-1 aggregation: agg1 = Â x (128 feats) ---------------
__global__ void k_agg1(const float* __restrict__ x, int n) {
    int node = (blockIdx.x * blockDim.x + threadIdx.x) >> 5;
    int lane = threadIdx.x & 31;
    if (node >= n) return;
    int beg = g_rows[node];
    int cnt = g_cnt[node];
    float4 acc = make_float4(0.f, 0.f, 0.f, 0.f);
    for (int i = 0; i < cnt; i++) {
        int s = g_csrc[beg + i];
        float ws = g_dinv[s];
        float4 v = ((const float4*)x)[(size_t)s * 32 + lane];
        acc.x += ws * v.x; acc.y += ws * v.y; acc.z += ws * v.z; acc.w += ws * v.w;
    }
    float wd = g_dinv[node];
    float4 xv = ((const float4*)x)[(size_t)node * 32 + lane];
    float4 o;
    o.x = tf32r(wd * (acc.x + wd * xv.x));
    o.y = tf32r(wd * (acc.y + wd * xv.y));
    o.z = tf32r(wd * (acc.z + wd * xv.z));
    o.w = tf32r(wd * (acc.w + wd * xv.w));
    ((float4*)g_agg1)[(size_t)node * 32 + lane] = o;
}

// ---------------- mma.sync tf32 GEMM: C[M,NT] = A[M,KD] * Bt[NT,KD]^T -------
// BM=128, BK=32, 256 threads, warp grid 4(M) x 2(N), warp tile 32 x (BN/2).
// m16n8k8 tf32 fragments; SMEM tiles stored pre-permuted into fragment order.
// MODE 1: C = tf32r(relu(C + bias)). MODE 0: plain. Stores only cols < NSTORE.
template <int NT, int BN, int KD, int MODE, int NSTORE>
__global__ void __launch_bounds__(256)
k_mmagemm(const float* __restrict__ A, const float* __restrict__ Bt,
          const float* __restrict__ bias, float* __restrict__ C, int M)
{
    constexpr int WN = BN / 2;              // warp N extent
    constexpr int NB = WN / 8;              // n-atoms per warp
    constexpr int AS = 8 * 128 + 8;         // A kstep stride (floats), pad 8
    constexpr int BS = (BN / 8) * 64 + 8;   // B kstep stride (floats), pad 8
    constexpr int BI = BN / 32;             // B prefetch float4s per thread
    constexpr int KT = KD / 32;             // BK iterations

    __shared__ float sA[4 * AS];
    __shared__ float sB[4 * BS];

    int tid  = threadIdx.x;
    int lane = tid & 31, wid = tid >> 5;
    int wm = wid & 3, wn = wid >> 2;
    int m0 = blockIdx.y * 128;
    int n0 = blockIdx.x * BN;

    float acc[2][NB][4];
    #pragma unroll
    for (int a = 0; a < 2; a++)
        #pragma unroll
        for (int b = 0; b < NB; b++)
            #pragma unroll
            for (int j = 0; j < 4; j++) acc[a][b][j] = 0.f;

    int lr = tid >> 3, lc4 = tid & 7;
    int kstep = lc4 >> 1;

    float4 pa[4], pb[BI];

    // prefetch tile 0
    #pragma unroll
    for (int i = 0; i < 4; i++) {
        int r = lr + 32 * i;
        pa[i] = (m0 + r < M)
              ? *(const float4*)(A + (size_t)(m0 + r) * KD + lc4 * 4)
              : make_float4(0.f, 0.f, 0.f, 0.f);
    }
    #pragma unroll
    for (int i = 0; i < BI; i++) {
        int n = lr + 32 * i;
        pb[i] = *(const float4*)(Bt + (size_t)(n0 + n) * KD + lc4 * 4);
    }

    for (int kt = 0; kt < KT; kt++) {
        __syncthreads();
        // ---- store prefetched tile into fragment-permuted SMEM ----
        {
            int regAb = 2 * (lc4 & 1);
            #pragma unroll
            for (int i = 0; i < 4; i++) {
                int r = lr + 32 * i;
                int rw = r & 15, matom = r >> 4;
                float* p = sA + kstep * AS + matom * 128 + (rw & 7) * 16
                         + (rw >> 3) + regAb;
                p[0] = pa[i].x; p[4] = pa[i].y; p[8] = pa[i].z; p[12] = pa[i].w;
            }
            int regB = lc4 & 1;
            #pragma unroll
            for (int i = 0; i < BI; i++) {
                int n = lr + 32 * i;
                float* p = sB + kstep * BS + (n >> 3) * 64 + (n & 7) * 8 + regB;
                p[0] = pb[i].x; p[2] = pb[i].y; p[4] = pb[i].z; p[6] = pb[i].w;
            }
        }
        __syncthreads();

        // ---- prefetch next tile ----
        if (kt + 1 < KT) {
            #pragma unroll
            for (int i = 0; i < 4; i++) {
                int r = lr + 32 * i;
                pa[i] = (m0 + r < M)
                      ? *(const float4*)(A + (size_t)(m0 + r) * KD
                                         + (kt + 1) * 32 + lc4 * 4)
                      : make_float4(0.f, 0.f, 0.f, 0.f);
            }
            #pragma unroll
            for (int i = 0; i < BI; i++) {
                int n = lr + 32 * i;
                pb[i] = *(const float4*)(Bt + (size_t)(n0 + n) * KD
                                         + (kt + 1) * 32 + lc4 * 4);
            }
        }

        // ---- compute: 4 k8-steps ----
        #pragma unroll
        for (int ks = 0; ks < 4; ks++) {
            uint32_t af[2][4];
            uint32_t bf[NB][2];
            #pragma unroll
            for (int a = 0; a < 2; a++)
                *(float4*)af[a] = *(const float4*)(sA + ks * AS
                                                   + (wm * 2 + a) * 128 + lane * 4);
            #pragma unroll
            for (int b = 0; b < NB; b++)
                *(float2*)bf[b] = *(const float2*)(sB + ks * BS
                                                   + (wn * NB + b) * 64 + lane * 2);
            #pragma unroll
            for (int a = 0; a < 2; a++)
                #pragma unroll
                for (int b = 0; b < NB; b++) {
                    asm volatile(
                        "mma.sync.aligned.m16n8k8.row.col.f32.tf32.tf32.f32 "
                        "{%0,%1,%2,%3}, {%4,%5,%6,%7}, {%8,%9}, {%0,%1,%2,%3};"
                        : "+f"(acc[a][b][0]), "+f"(acc[a][b][1]),
                          "+f"(acc[a][b][2]), "+f"(acc[a][b][3])
                        : "r"(af[a][0]), "r"(af[a][1]), "r"(af[a][2]), "r"(af[a][3]),
                          "r"(bf[b][0]), "r"(bf[b][1]));
                }
        }
    }

    // ---- epilogue ----
    int rbase = m0 + wm * 32 + (lane >> 2);
    #pragma unroll
    for (int a = 0; a < 2; a++) {
        int r1 = rbase + a * 16;
        int r2 = r1 + 8;
        #pragma unroll
        for (int b = 0; b < NB; b++) {
            int col = n0 + wn * WN + b * 8 + (lane & 3) * 2;
            if (col >= NSTORE) continue;
            float v0 = acc[a][b][0], v1 = acc[a][b][1];
            float v2 = acc[a][b][2], v3 = acc[a][b][3];
            if (MODE == 1) {
                float bb0 = __ldg(&bias[col]), bb1 = __ldg(&bias[col + 1]);
                v0 = tf32r(fmaxf(v0 + bb0, 0.f));
                v1 = tf32r(fmaxf(v1 + bb1, 0.f));
                v2 = tf32r(fmaxf(v2 + bb0, 0.f));
                v3 = tf32r(fmaxf(v3 + bb1, 0.f));
            }
            if (r1 < M) *(float2*)(C + (size_t)r1 * NT + col) = make_float2(v0, v1);
            if (r2 < M) *(float2*)(C + (size_t)r2 * NT + col) = make_float2(v2, v3);
        }
    }
}

// ---------------- layer-2 aggregation + bias + log_softmax -----------------
__global__ void k_agg2_softmax(const float* __restrict__ b2,
                               float* __restrict__ out, int n) {
    int node = (blockIdx.x * blockDim.x + threadIdx.x) >> 5;
    int lane = threadIdx.x & 31;
    if (node >= n) return;
    int beg = g_rows[node];
    int cnt = g_cnt[node];
    float a0 = 0.f, a1 = 0.f;
    for (int i = 0; i < cnt; i++) {
        int s = g_csrc[beg + i];
        float ws = g_dinv[s];
        const float* row = g_l2h + (size_t)s * NPAD;
        a0 += ws * row[lane];
        if (lane < 8) a1 += ws * row[32 + lane];
    }
    float wd = g_dinv[node];
    const float* srow = g_l2h + (size_t)node * NPAD;
    float v0 = b2[lane] + wd * (a0 + wd * srow[lane]);
    float v1 = -1e30f;
    if (lane < 8) v1 = b2[32 + lane] + wd * (a1 + wd * srow[32 + lane]);

    float m = fmaxf(v0, v1);
    #pragma unroll
    for (int off = 16; off; off >>= 1)
        m = fmaxf(m, __shfl_xor_sync(0xffffffffu, m, off));
    float e = expf(v0 - m) + ((lane < 8) ? expf(v1 - m) : 0.f);
    #pragma unroll
    for (int off = 16; off; off >>= 1)
        e += __shfl_xor_sync(0xffffffffu, e, off);
    float lse = m + logf(e);

    out[(size_t)node * NCLS + lane] = v0 - lse;
    if (lane < 8) out[(size_t)node * NCLS + 32 + lane] = v1 - lse;
}

// ---------------- host ------------------------------------------------------
extern "C" void kernel_launch(void* const* d_in, const int* in_sizes, int n_in,
                              void* d_out, int out_size) {
    const float* x  = (const float*)d_in[0];
    const int*   ei = (const int*)d_in[1];
    const float* W1 = (const float*)d_in[2];
    const float* b1 = (const float*)d_in[3];
    const float* W2 = (const float*)d_in[4];
    const float* b2 = (const float*)d_in[5];
    float* out = (float*)d_out;

    int N = in_sizes[0] / F1;
    int E = in_sizes[1] / 2;
    const int* src = ei;
    const int* dst = ei + E;

    float *p_agg1, *p_h1, *p_l2h, *p_w1t, *p_w2t;
    cudaGetSymbolAddress((void**)&p_agg1, g_agg1);
    cudaGetSymbolAddress((void**)&p_h1,   g_h1);
    cudaGetSymbolAddress((void**)&p_l2h,  g_l2h);
    cudaGetSymbolAddress((void**)&p_w1t,  g_w1t);
    cudaGetSymbolAddress((void**)&p_w2t,  g_w2t);

    int nb = (N + 1023) / 1024;
    int ntiles = (N + 127) / 128;

    k_zero_cnt<<<(N + 255) / 256, 256>>>(N);
    k_count  <<<(E + 255) / 256, 256>>>(dst, E);
    k_dinv   <<<(N + 255) / 256, 256>>>(N);
    k_scan1  <<<nb, 1024>>>(N);
    k_scan2  <<<1, 128>>>(nb);
    k_scan3  <<<(N + 255) / 256, 256>>>(N);
    k_fill   <<<(E + 255) / 256, 256>>>(src, dst, E);

    k_w1t<<<(HID * F1 + 255) / 256, 256>>>(W1);
    k_w2t<<<(NPAD * HID + 255) / 256, 256>>>(W2);

    // layer 1: aggregate(x) -> tensor-core GEMM(+bias, relu)
    k_agg1<<<((size_t)N * 32 + 255) / 256, 256>>>(x, N);
    {
        dim3 grid(HID / 128, ntiles);
        k_mmagemm<HID, 128, F1, 1, HID><<<grid, 256>>>(p_agg1, p_w1t, b1, p_h1, N);
    }

    // layer 2: tensor-core GEMM (padded 40->64) -> aggregate + log_softmax
    {
        dim3 grid(1, ntiles);
        k_mmagemm<NPAD, 64, HID, 0, NCLS><<<grid, 256>>>(p_h1, p_w2t, nullptr, p_l2h, N);
    }
    k_agg2_softmax<<<((size_t)N * 32 + 255) / 256, 256>>>(b2, out, N);
}

// round 10
// speedup vs baseline: 1.6078x; 1.0710x over previous
#include <cuda_runtime.h>
#include <cstdint>

// Problem constants (shapes fixed by the dataset).
#define NMAX   100000
#define EMAX   800000
#define F1     128      // input features
#define HID    256      // hidden
#define NCLS   40       // classes
#define NPAD   64       // padded classes

// ---------------- scratch (device globals; no allocation allowed) ----------
__device__ float g_dinv[NMAX];
__device__ int   g_cnt[NMAX];
__device__ int   g_rows[NMAX];
__device__ int   g_cursor[NMAX];
__device__ int   g_csrc[EMAX];
__device__ int   g_bsum[128];
__device__ float g_agg1[(size_t)NMAX * F1];   // 51.2 MB (tf32-rounded)
__device__ float g_l2h [(size_t)NMAX * NPAD]; // 25.6 MB
__device__ float g_w1t [HID * F1];            // W1^T  [256][128] tf32
__device__ float g_w2t [NPAD * HID];          // W2^T padded [64][256] tf32

// ---------------- small helpers --------------------------------------------
__device__ __forceinline__ float tf32r(float x) {
    uint32_t u;
    asm("cvt.rna.tf32.f32 %0, %1;" : "=r"(u) : "f"(x));
    return __uint_as_float(u);
}

// ---------------- degree / CSR build ---------------------------------------
__global__ void k_zero_cnt(int n) {
    int i = blockIdx.x * blockDim.x + threadIdx.x;
    if (i < n) g_cnt[i] = 0;
}

__global__ void k_count(const int* __restrict__ dst, int E) {
    int e = blockIdx.x * blockDim.x + threadIdx.x;
    if (e < E) atomicAdd(&g_cnt[dst[e]], 1);
}

__global__ void k_scan1(int n) {
    __shared__ int s[1024];
    int t = threadIdx.x;
    int i = blockIdx.x * 1024 + t;
    int v = (i < n) ? g_cnt[i] : 0;
    s[t] = v;
    __syncthreads();
    #pragma unroll
    for (int off = 1; off < 1024; off <<= 1) {
        int add = (t >= off) ? s[t - off] : 0;
        __syncthreads();
        s[t] += add;
        __syncthreads();
    }
    if (i < n) g_rows[i] = s[t];
    if (t == 1023) g_bsum[blockIdx.x] = s[1023];
}

__global__ void k_scan2(int nb) {
    __shared__ int s[128];
    int t = threadIdx.x;
    int v = (t < nb) ? g_bsum[t] : 0;
    s[t] = v;
    __syncthreads();
    #pragma unroll
    for (int off = 1; off < 128; off <<= 1) {
        int add = (t >= off) ? s[t - off] : 0;
        __syncthreads();
        s[t] += add;
        __syncthreads();
    }
    if (t < nb) g_bsum[t] = s[t] - v;
}

// scan finalize + dinv fused (both elementwise over nodes, cnt stable here)
__global__ void k_scan3(int n) {
    int i = blockIdx.x * blockDim.x + threadIdx.x;
    if (i < n) {
        int c = g_cnt[i];
        int excl = g_rows[i] - c + g_bsum[i >> 10];
        g_rows[i]   = excl;
        g_cursor[i] = excl;
        g_dinv[i]   = rsqrtf((float)(c + 1));
    }
}

__global__ void k_fill(const int* __restrict__ src, const int* __restrict__ dst, int E) {
    int e = blockIdx.x * blockDim.x + threadIdx.x;
    if (e < E) {
        int d = dst[e];
        int pos = atomicAdd(&g_cursor[d], 1);
        g_csrc[pos] = src[e];
    }
}

// ---------------- weight transpose + tf32 rounding (fused) ------------------
__global__ void k_wprep(const float* __restrict__ W1, const float* __restrict__ W2) {
    int t = blockIdx.x * blockDim.x + threadIdx.x;
    if (t < HID * F1) {
        int n = t / F1, k = t % F1;
        g_w1t[t] = tf32r(W1[k * HID + n]);
    } else if (t < HID * F1 + NPAD * HID) {
        int u = t - HID * F1;
        int n = u / HID, k = u % HID;
        g_w2t[u] = (n < NCLS) ? tf32r(W2[k * NCLS + n]) : 0.f;
    }
}

// ---------------- layer-1 aggregation: agg1 = Â x (128 feats) ---------------
__global__ void k_agg1(const float* __restrict__ x, int n) {
    int node = (blockIdx.x * blockDim.x + threadIdx.x) >> 5;
    int lane = threadIdx.x & 31;
    if (node >= n) return;
    int beg = g_rows[node];
    int cnt = g_cnt[node];
    float4 acc = make_float4(0.f, 0.f, 0.f, 0.f);
    for (int i = 0; i < cnt; i++) {
        int s = g_csrc[beg + i];
        float ws = g_dinv[s];
        float4 v = ((const float4*)x)[(size_t)s * 32 + lane];
        acc.x += ws * v.x; acc.y += ws * v.y; acc.z += ws * v.z; acc.w += ws * v.w;
    }
    float wd = g_dinv[node];
    float4 xv = ((const float4*)x)[(size_t)node * 32 + lane];
    float4 o;
    o.x = tf32r(wd * (acc.x + wd * xv.x));
    o.y = tf32r(wd * (acc.y + wd * xv.y));
    o.z = tf32r(wd * (acc.z + wd * xv.z));
    o.w = tf32r(wd * (acc.w + wd * xv.w));
    ((float4*)g_agg1)[(size_t)node * 32 + lane] = o;
}

// ---------------- fused 2-layer MLP on tensor cores -------------------------
// Per 128-row tile:
//   stage 1 (x2 halves): h_half = tf32r(relu(A(128x128) @ W1t_half^T + b1))
//     -> written into SMEM in stage-2 A-fragment-permuted layout
//   stage 2: acc2 += h_half @ W2t_half^T   (W2 fragments SMEM-resident)
// Final: store acc2 cols < NCLS to C (stride NPAD). g_h1 eliminated.
__global__ void __launch_bounds__(256)
k_fusedmlp(const float* __restrict__ A, const float* __restrict__ W1t,
           const float* __restrict__ b1, const float* __restrict__ W2t,
           float* __restrict__ C, int M)
{
    constexpr int AS  = 8 * 128 + 8;   // 1032 floats per kstep (A/h fragments)
    constexpr int BS1 = 16 * 64 + 8;   // 1032 (stage-1 B: 16 n-atoms)
    constexpr int BS2 = 8 * 64 + 8;    // 520  (stage-2 B: 8 n-atoms)
    extern __shared__ float sm[];
    float* sA  = sm;                   // 4*AS    (stage-1 A k-tiles)
    float* sB  = sA + 4 * AS;          // 4*BS1   (stage-1 B k-tiles)
    float* hb  = sB + 4 * BS1;         // 16*AS   (h half, stage-2 A fragments)
    float* w2b = hb + 16 * AS;         // 32*BS2  (full W2 fragments)

    int tid = threadIdx.x, lane = tid & 31, wid = tid >> 5;
    int wm = wid & 3, wn = wid >> 2;
    int m0 = blockIdx.x * 128;

    // ---- load W2t (64x256) into fragment-permuted w2b (once per CTA) ----
    for (int idx = tid; idx < 64 * 64; idx += 256) {
        int n = idx >> 6, c4 = idx & 63;
        float4 v = *(const float4*)(W2t + n * HID + c4 * 4);
        float* p = w2b + (c4 >> 1) * BS2 + (n >> 3) * 64 + (n & 7) * 8 + (c4 & 1);
        p[0] = v.x; p[2] = v.y; p[4] = v.z; p[6] = v.w;
    }
    // (first w2b read is in stage 2; kt-loop __syncthreads below cover ordering)

    float acc2[2][4][4];
    #pragma unroll
    for (int a = 0; a < 2; a++)
        #pragma unroll
        for (int b = 0; b < 4; b++)
            #pragma unroll
            for (int j = 0; j < 4; j++) acc2[a][b][j] = 0.f;

    int lr = tid >> 3, lc4 = tid & 7, kstep = lc4 >> 1;

    #pragma unroll 1
    for (int h2 = 0; h2 < 2; h2++) {
        const float* Bt = W1t + (size_t)(h2 * 128) * F1;   // 128 hidden rows
        float acc[2][8][4];
        #pragma unroll
        for (int a = 0; a < 2; a++)
            #pragma unroll
            for (int b = 0; b < 8; b++)
                #pragma unroll
                for (int j = 0; j < 4; j++) acc[a][b][j] = 0.f;

        float4 pa[4], pb[4];
        #pragma unroll
        for (int i = 0; i < 4; i++) {
            int r = lr + 32 * i;
            pa[i] = (m0 + r < M)
                  ? *(const float4*)(A + (size_t)(m0 + r) * F1 + lc4 * 4)
                  : make_float4(0.f, 0.f, 0.f, 0.f);
        }
        #pragma unroll
        for (int i = 0; i < 4; i++) {
            int n = lr + 32 * i;
            pb[i] = *(const float4*)(Bt + (size_t)n * F1 + lc4 * 4);
        }

        for (int kt = 0; kt < 4; kt++) {
            __syncthreads();
            {   // store prefetched tile in fragment-permuted order
                int regAb = 2 * (lc4 & 1);
                #pragma unroll
                for (int i = 0; i < 4; i++) {
                    int r = lr + 32 * i, rw = r & 15, matom = r >> 4;
                    float* p = sA + kstep * AS + matom * 128 + (rw & 7) * 16
                             + (rw >> 3) + regAb;
                    p[0] = pa[i].x; p[4] = pa[i].y; p[8] = pa[i].z; p[12] = pa[i].w;
                }
                int regB = lc4 & 1;
                #pragma unroll
                for (int i = 0; i < 4; i++) {
                    int n = lr + 32 * i;
                    float* p = sB + kstep * BS1 + (n >> 3) * 64 + (n & 7) * 8 + regB;
                    p[0] = pb[i].x; p[2] = pb[i].y; p[4] = pb[i].z; p[6] = pb[i].w;
                }
            }
            __syncthreads();
            if (kt + 1 < 4) {
                #pragma unroll
                for (int i = 0; i < 4; i++) {
                    int r = lr + 32 * i;
                    pa[i] = (m0 + r < M)
                          ? *(const float4*)(A + (size_t)(m0 + r) * F1
                                             + (kt + 1) * 32 + lc4 * 4)
                          : make_float4(0.f, 0.f, 0.f, 0.f);
                }
                #pragma unroll
                for (int i = 0; i < 4; i++) {
                    int n = lr + 32 * i;
                    pb[i] = *(const float4*)(Bt + (size_t)n * F1
                                             + (kt + 1) * 32 + lc4 * 4);
                }
            }
            #pragma unroll
            for (int ks = 0; ks < 4; ks++) {
                uint32_t af[2][4], bf[8][2];
                #pragma unroll
                for (int a = 0; a < 2; a++)
                    *(float4*)af[a] = *(const float4*)(sA + ks * AS
                                                       + (wm * 2 + a) * 128 + lane * 4);
                #pragma unroll
                for (int b = 0; b < 8; b++)
                    *(float2*)bf[b] = *(const float2*)(sB + ks * BS1
                                                       + (wn * 8 + b) * 64 + lane * 2);
                #pragma unroll
                for (int a = 0; a < 2; a++)
                    #pragma unroll
                    for (int b = 0; b < 8; b++) {
                        asm volatile(
                            "mma.sync.aligned.m16n8k8.row.col.f32.tf32.tf32.f32 "
                            "{%0,%1,%2,%3}, {%4,%5,%6,%7}, {%8,%9}, {%0,%1,%2,%3};"
                            : "+f"(acc[a][b][0]), "+f"(acc[a][b][1]),
                              "+f"(acc[a][b][2]), "+f"(acc[a][b][3])
                            : "r"(af[a][0]), "r"(af[a][1]), "r"(af[a][2]), "r"(af[a][3]),
                              "r"(bf[b][0]), "r"(bf[b][1]));
                    }
            }
        }

        // ---- stage-1 epilogue: bias+relu+tf32 -> hb (stage-2 A fragments) ----
        {
            int rb = wm * 32 + (lane >> 2);
            #pragma unroll
            for (int a = 0; a < 2; a++) {
                #pragma unroll
                for (int b = 0; b < 8; b++) {
                    int colL = wn * 64 + b * 8 + (lane & 3) * 2;
                    float bb0 = __ldg(&b1[h2 * 128 + colL]);
                    float bb1 = __ldg(&b1[h2 * 128 + colL + 1]);
                    #pragma unroll
                    for (int j = 0; j < 4; j++) {
                        int r = rb + a * 16 + ((j >> 1) << 3);
                        int c = colL + (j & 1);
                        float v = tf32r(fmaxf(acc[a][b][j] + ((j & 1) ? bb1 : bb0), 0.f));
                        int rw = r & 15;
                        hb[(c >> 3) * AS + (r >> 4) * 128 + (rw & 7) * 16 + (rw >> 3)
                           + 2 * ((c >> 2) & 1) + 4 * (c & 3)] = v;
                    }
                }
            }
        }
        __syncthreads();

        // ---- stage 2: acc2 += h_half @ W2_half^T (all SMEM) ----
        #pragma unroll
        for (int kt2 = 0; kt2 < 4; kt2++) {
            #pragma unroll
            for (int ks = 0; ks < 4; ks++) {
                int g = kt2 * 4 + ks;
                uint32_t af[2][4], bf[4][2];
                #pragma unroll
                for (int a = 0; a < 2; a++)
                    *(float4*)af[a] = *(const float4*)(hb + g * AS
                                                       + (wm * 2 + a) * 128 + lane * 4);
                #pragma unroll
                for (int b = 0; b < 4; b++)
                    *(float2*)bf[b] = *(const float2*)(w2b + (h2 * 16 + g) * BS2
                                                       + (wn * 4 + b) * 64 + lane * 2);
                #pragma unroll
                for (int a = 0; a < 2; a++)
                    #pragma unroll
                    for (int b = 0; b < 4; b++) {
                        asm volatile(
                            "mma.sync.aligned.m16n8k8.row.col.f32.tf32.tf32.f32 "
                            "{%0,%1,%2,%3}, {%4,%5,%6,%7}, {%8,%9}, {%0,%1,%2,%3};"
                            : "+f"(acc2[a][b][0]), "+f"(acc2[a][b][1]),
                              "+f"(acc2[a][b][2]), "+f"(acc2[a][b][3])
                            : "r"(af[a][0]), "r"(af[a][1]), "r"(af[a][2]), "r"(af[a][3]),
                              "r"(bf[b][0]), "r"(bf[b][1]));
                    }
            }
        }
    }

    // ---- final store: logits cols < NCLS ----
    int rbase = m0 + wm * 32 + (lane >> 2);
    #pragma unroll
    for (int a = 0; a < 2; a++) {
        int r1 = rbase + a * 16;
        int r2 = r1 + 8;
        #pragma unroll
        for (int b = 0; b < 4; b++) {
            int col = wn * 32 + b * 8 + (lane & 3) * 2;
            if (col >= NCLS) continue;
            if (r1 < M) *(float2*)(C + (size_t)r1 * NPAD + col)
                      = make_float2(acc2[a][b][0], acc2[a][b][1]);
            if (r2 < M) *(float2*)(C + (size_t)r2 * NPAD + col)
                      = make_float2(acc2[a][b][2], acc2[a][b][3]);
        }
    }
}

// ---------------- layer-2 aggregation + bias + log_softmax -----------------
__global__ void k_agg2_softmax(const float* __restrict__ b2,
                               float* __restrict__ out, int n) {
    int node = (blockIdx.x * blockDim.x + threadIdx.x) >> 5;
    int lane = threadIdx.x & 31;
    if (node >= n) return;
    int beg = g_rows[node];
    int cnt = g_cnt[node];
    float a0 = 0.f, a1 = 0.f;
    for (int i = 0; i < cnt; i++) {
        int s = g_csrc[beg + i];
        float ws = g_dinv[s];
        const float* row = g_l2h + (size_t)s * NPAD;
        a0 += ws * row[lane];
        if (lane < 8) a1 += ws * row[32 + lane];
    }
    float wd = g_dinv[node];
    const float* srow = g_l2h + (size_t)node * NPAD;
    float v0 = b2[lane] + wd * (a0 + wd * srow[lane]);
    float v1 = -1e30f;
    if (lane < 8) v1 = b2[32 + lane] + wd * (a1 + wd * srow[32 + lane]);

    float m = fmaxf(v0, v1);
    #pragma unroll
    for (int off = 16; off; off >>= 1)
        m = fmaxf(m, __shfl_xor_sync(0xffffffffu, m, off));
    float e = expf(v0 - m) + ((lane < 8) ? expf(v1 - m) : 0.f);
    #pragma unroll
    for (int off = 16; off; off >>= 1)
        e += __shfl_xor_sync(0xffffffffu, e, off);
    float lse = m + logf(e);

    out[(size_t)node * NCLS + lane] = v0 - lse;
    if (lane < 8) out[(size_t)node * NCLS + 32 + lane] = v1 - lse;
}

// ---------------- host ------------------------------------------------------
extern "C" void kernel_launch(void* const* d_in, const int* in_sizes, int n_in,
                              void* d_out, int out_size) {
    const float* x  = (const float*)d_in[0];
    const int*   ei = (const int*)d_in[1];
    const float* W1 = (const float*)d_in[2];
    const float* b1 = (const float*)d_in[3];
    const float* W2 = (const float*)d_in[4];
    const float* b2 = (const float*)d_in[5];
    float* out = (float*)d_out;

    int N = in_sizes[0] / F1;
    int E = in_sizes[1] / 2;
    const int* src = ei;
    const int* dst = ei + E;

    float *p_agg1, *p_l2h, *p_w1t, *p_w2t;
    cudaGetSymbolAddress((void**)&p_agg1, g_agg1);
    cudaGetSymbolAddress((void**)&p_l2h,  g_l2h);
    cudaGetSymbolAddress((void**)&p_w1t,  g_w1t);
    cudaGetSymbolAddress((void**)&p_w2t,  g_w2t);

    // fused-MLP dynamic SMEM: (4+16)*1032 + 4*1032 + 32*520 floats
    const int SMEMF = (24 * 1032 + 32 * 520) * 4;   // 165,632 B
    static int configured = 0;
    cudaFuncSetAttribute(k_fusedmlp,
                         cudaFuncAttributeMaxDynamicSharedMemorySize, SMEMF);
    (void)configured;

    int nb = (N + 1023) / 1024;
    int ntiles = (N + 127) / 128;

    k_zero_cnt<<<(N + 255) / 256, 256>>>(N);
    k_count  <<<(E + 255) / 256, 256>>>(dst, E);
    k_scan1  <<<nb, 1024>>>(N);
    k_scan2  <<<1, 128>>>(nb);
    k_scan3  <<<(N + 255) / 256, 256>>>(N);
    k_fill   <<<(E + 255) / 256, 256>>>(src, dst, E);

    k_wprep<<<(HID * F1 + NPAD * HID + 255) / 256, 256>>>(W1, W2);

    // layer 1 aggregate -> fused GEMM1+relu+GEMM2 (h1 never hits DRAM)
    k_agg1<<<((size_t)N * 32 + 255) / 256, 256>>>(x, N);
    k_fusedmlp<<<ntiles, 256, SMEMF>>>(p_agg1, p_w1t, b1, p_w2t, p_l2h, N);

    // aggregate logits + bias + log_softmax
    k_agg2_softmax<<<((size_t)N * 32 + 255) / 256, 256>>>(b2, out, N);
}

// round 11
// speedup vs baseline: 1.6173x; 1.0059x over previous
#include <cuda_runtime.h>
#include <cstdint>

// Problem constants (shapes fixed by the dataset).
#define NMAX   100000
#define EMAX   800000
#define F1     128      // input features
#define HID    256      // hidden
#define NCLS   40       // classes
#define NPAD   64       // padded classes

// ---------------- scratch (device globals; no allocation allowed) ----------
__device__ float g_dinv[NMAX];
__device__ int   g_cnt[NMAX];
__device__ int   g_rows[NMAX];
__device__ int   g_cursor[NMAX];
__device__ int   g_csrc[EMAX];
__device__ int   g_total;
__device__ float g_agg1[(size_t)NMAX * F1];   // 51.2 MB (tf32-rounded)
__device__ float g_l2h [(size_t)NMAX * NPAD]; // 25.6 MB
__device__ float g_w1t [HID * F1];            // W1^T  [256][128] tf32
__device__ float g_w2t [NPAD * HID];          // W2^T padded [64][256] tf32

// ---------------- small helpers --------------------------------------------
__device__ __forceinline__ float tf32r(float x) {
    uint32_t u;
    asm("cvt.rna.tf32.f32 %0, %1;" : "=r"(u) : "f"(x));
    return __uint_as_float(u);
}

// ---------------- fused: degree count + weight prep + total reset -----------
__global__ void k_count_wprep(const int* __restrict__ dst, int E,
                              const float* __restrict__ W1,
                              const float* __restrict__ W2) {
    int t = blockIdx.x * blockDim.x + threadIdx.x;
    if (t == 0) g_total = 0;
    if (t < E) atomicAdd(&g_cnt[dst[t]], 1);
    if (t < HID * F1) {
        int n = t / F1, k = t % F1;
        g_w1t[t] = tf32r(W1[k * HID + n]);
    } else if (t < HID * F1 + NPAD * HID) {
        int u = t - HID * F1;
        int n = u / HID, k = u % HID;
        g_w2t[u] = (n < NCLS) ? tf32r(W2[k * NCLS + n]) : 0.f;
    }
}

// ---------------- segment assignment: block scan + atomic base --------------
// Replaces scan1/scan2/scan3+dinv. Segment placement order is not node-sorted
// (atomic base), which is fine: only per-node membership matters downstream.
__global__ void k_scan_assign(int n) {
    __shared__ int s[1024];
    __shared__ int base;
    int t = threadIdx.x;
    int i = blockIdx.x * 1024 + t;
    int c = (i < n) ? g_cnt[i] : 0;
    s[t] = c;
    __syncthreads();
    #pragma unroll
    for (int off = 1; off < 1024; off <<= 1) {
        int add = (t >= off) ? s[t - off] : 0;
        __syncthreads();
        s[t] += add;
        __syncthreads();
    }
    int incl = s[t];
    if (t == 1023) base = atomicAdd(&g_total, s[1023]);
    __syncthreads();
    if (i < n) {
        int beg = base + incl - c;
        g_rows[i]   = beg;
        g_cursor[i] = beg;
        g_dinv[i]   = rsqrtf((float)(c + 1));
    }
}

__global__ void k_fill(const int* __restrict__ src, const int* __restrict__ dst, int E) {
    int e = blockIdx.x * blockDim.x + threadIdx.x;
    if (e < E) {
        int d = dst[e];
        int pos = atomicAdd(&g_cursor[d], 1);
        g_csrc[pos] = src[e];
    }
}

// ---------------- layer-1 aggregation: agg1 = Â x (128 feats) ---------------
// one warp per node; 4x unrolled edge loop for memory-level parallelism
__global__ void k_agg1(const float* __restrict__ x, int n) {
    int node = (blockIdx.x * blockDim.x + threadIdx.x) >> 5;
    int lane = threadIdx.x & 31;
    if (node >= n) return;
    int beg = g_rows[node];
    int cnt = g_cnt[node];
    float4 acc = make_float4(0.f, 0.f, 0.f, 0.f);
    int i = 0;
    for (; i + 4 <= cnt; i += 4) {
        int s0 = g_csrc[beg + i + 0];
        int s1 = g_csrc[beg + i + 1];
        int s2 = g_csrc[beg + i + 2];
        int s3 = g_csrc[beg + i + 3];
        float w0 = g_dinv[s0], w1 = g_dinv[s1];
        float w2 = g_dinv[s2], w3 = g_dinv[s3];
        float4 v0 = ((const float4*)x)[(size_t)s0 * 32 + lane];
        float4 v1 = ((const float4*)x)[(size_t)s1 * 32 + lane];
        float4 v2 = ((const float4*)x)[(size_t)s2 * 32 + lane];
        float4 v3 = ((const float4*)x)[(size_t)s3 * 32 + lane];
        acc.x += w0 * v0.x + w1 * v1.x + w2 * v2.x + w3 * v3.x;
        acc.y += w0 * v0.y + w1 * v1.y + w2 * v2.y + w3 * v3.y;
        acc.z += w0 * v0.z + w1 * v1.z + w2 * v2.z + w3 * v3.z;
        acc.w += w0 * v0.w + w1 * v1.w + w2 * v2.w + w3 * v3.w;
    }
    for (; i < cnt; i++) {
        int s = g_csrc[beg + i];
        float ws = g_dinv[s];
        float4 v = ((const float4*)x)[(size_t)s * 32 + lane];
        acc.x += ws * v.x; acc.y += ws * v.y; acc.z += ws * v.z; acc.w += ws * v.w;
    }
    float wd = g_dinv[node];
    float4 xv = ((const float4*)x)[(size_t)node * 32 + lane];
    float4 o;
    o.x = tf32r(wd * (acc.x + wd * xv.x));
    o.y = tf32r(wd * (acc.y + wd * xv.y));
    o.z = tf32r(wd * (acc.z + wd * xv.z));
    o.w = tf32r(wd * (acc.w + wd * xv.w));
    ((float4*)g_agg1)[(size_t)node * 32 + lane] = o;
}

// ---------------- fused 2-layer MLP on tensor cores -------------------------
// Per 128-row tile:
//   stage 1 (x2 halves): h_half = tf32r(relu(A(128x128) @ W1t_half^T + b1))
//     -> written into SMEM in stage-2 A-fragment-permuted layout
//   stage 2: acc2 += h_half @ W2t_half^T   (W2 fragments SMEM-resident)
// Final: store acc2 cols < NCLS to C (stride NPAD). h1 never hits DRAM.
__global__ void __launch_bounds__(256)
k_fusedmlp(const float* __restrict__ A, const float* __restrict__ W1t,
           const float* __restrict__ b1, const float* __restrict__ W2t,
           float* __restrict__ C, int M)
{
    constexpr int AS  = 8 * 128 + 8;   // 1032 floats per kstep (A/h fragments)
    constexpr int BS1 = 16 * 64 + 8;   // 1032 (stage-1 B: 16 n-atoms)
    constexpr int BS2 = 8 * 64 + 8;    // 520  (stage-2 B: 8 n-atoms)
    extern __shared__ float sm[];
    float* sA  = sm;                   // 4*AS    (stage-1 A k-tiles)
    float* sB  = sA + 4 * AS;          // 4*BS1   (stage-1 B k-tiles)
    float* hb  = sB + 4 * BS1;         // 16*AS   (h half, stage-2 A fragments)
    float* w2b = hb + 16 * AS;         // 32*BS2  (full W2 fragments)

    int tid = threadIdx.x, lane = tid & 31, wid = tid >> 5;
    int wm = wid & 3, wn = wid >> 2;
    int m0 = blockIdx.x * 128;

    // ---- load W2t (64x256) into fragment-permuted w2b (once per CTA) ----
    for (int idx = tid; idx < 64 * 64; idx += 256) {
        int n = idx >> 6, c4 = idx & 63;
        float4 v = *(const float4*)(W2t + n * HID + c4 * 4);
        float* p = w2b + (c4 >> 1) * BS2 + (n >> 3) * 64 + (n & 7) * 8 + (c4 & 1);
        p[0] = v.x; p[2] = v.y; p[4] = v.z; p[6] = v.w;
    }
    // (first w2b read is in stage 2; kt-loop __syncthreads below cover ordering)

    float acc2[2][4][4];
    #pragma unroll
    for (int a = 0; a < 2; a++)
        #pragma unroll
        for (int b = 0; b < 4; b++)
            #pragma unroll
            for (int j = 0; j < 4; j++) acc2[a][b][j] = 0.f;

    int lr = tid >> 3, lc4 = tid & 7, kstep = lc4 >> 1;

    #pragma unroll 1
    for (int h2 = 0; h2 < 2; h2++) {
        const float* Bt = W1t + (size_t)(h2 * 128) * F1;   // 128 hidden rows
        float acc[2][8][4];
        #pragma unroll
        for (int a = 0; a < 2; a++)
            #pragma unroll
            for (int b = 0; b < 8; b++)
                #pragma unroll
                for (int j = 0; j < 4; j++) acc[a][b][j] = 0.f;

        float4 pa[4], pb[4];
        #pragma unroll
        for (int i = 0; i < 4; i++) {
            int r = lr + 32 * i;
            pa[i] = (m0 + r < M)
                  ? *(const float4*)(A + (size_t)(m0 + r) * F1 + lc4 * 4)
                  : make_float4(0.f, 0.f, 0.f, 0.f);
        }
        #pragma unroll
        for (int i = 0; i < 4; i++) {
            int n = lr + 32 * i;
            pb[i] = *(const float4*)(Bt + (size_t)n * F1 + lc4 * 4);
        }

        for (int kt = 0; kt < 4; kt++) {
            __syncthreads();
            {   // store prefetched tile in fragment-permuted order
                int regAb = 2 * (lc4 & 1);
                #pragma unroll
                for (int i = 0; i < 4; i++) {
                    int r = lr + 32 * i, rw = r & 15, matom = r >> 4;
                    float* p = sA + kstep * AS + matom * 128 + (rw & 7) * 16
                             + (rw >> 3) + regAb;
                    p[0] = pa[i].x; p[4] = pa[i].y; p[8] = pa[i].z; p[12] = pa[i].w;
                }
                int regB = lc4 & 1;
                #pragma unroll
                for (int i = 0; i < 4; i++) {
                    int n = lr + 32 * i;
                    float* p = sB + kstep * BS1 + (n >> 3) * 64 + (n & 7) * 8 + regB;
                    p[0] = pb[i].x; p[2] = pb[i].y; p[4] = pb[i].z; p[6] = pb[i].w;
                }
            }
            __syncthreads();
            if (kt + 1 < 4) {
                #pragma unroll
                for (int i = 0; i < 4; i++) {
                    int r = lr + 32 * i;
                    pa[i] = (m0 + r < M)
                          ? *(const float4*)(A + (size_t)(m0 + r) * F1
                                             + (kt + 1) * 32 + lc4 * 4)
                          : make_float4(0.f, 0.f, 0.f, 0.f);
                }
                #pragma unroll
                for (int i = 0; i < 4; i++) {
                    int n = lr + 32 * i;
                    pb[i] = *(const float4*)(Bt + (size_t)n * F1
                                             + (kt + 1) * 32 + lc4 * 4);
                }
            }
            #pragma unroll
            for (int ks = 0; ks < 4; ks++) {
                uint32_t af[2][4], bf[8][2];
                #pragma unroll
                for (int a = 0; a < 2; a++)
                    *(float4*)af[a] = *(const float4*)(sA + ks * AS
                                                       + (wm * 2 + a) * 128 + lane * 4);
                #pragma unroll
                for (int b = 0; b < 8; b++)
                    *(float2*)bf[b] = *(const float2*)(sB + ks * BS1
                                                       + (wn * 8 + b) * 64 + lane * 2);
                #pragma unroll
                for (int a = 0; a < 2; a++)
                    #pragma unroll
                    for (int b = 0; b < 8; b++) {
                        asm volatile(
                            "mma.sync.aligned.m16n8k8.row.col.f32.tf32.tf32.f32 "
                            "{%0,%1,%2,%3}, {%4,%5,%6,%7}, {%8,%9}, {%0,%1,%2,%3};"
                            : "+f"(acc[a][b][0]), "+f"(acc[a][b][1]),
                              "+f"(acc[a][b][2]), "+f"(acc[a][b][3])
                            : "r"(af[a][0]), "r"(af[a][1]), "r"(af[a][2]), "r"(af[a][3]),
                              "r"(bf[b][0]), "r"(bf[b][1]));
                    }
            }
        }

        // ---- stage-1 epilogue: bias+relu+tf32 -> hb (stage-2 A fragments) ----
        {
            int rb = wm * 32 + (lane >> 2);
            #pragma unroll
            for (int a = 0; a < 2; a++) {
                #pragma unroll
                for (int b = 0; b < 8; b++) {
                    int colL = wn * 64 + b * 8 + (lane & 3) * 2;
                    float bb0 = __ldg(&b1[h2 * 128 + colL]);
                    float bb1 = __ldg(&b1[h2 * 128 + colL + 1]);
                    #pragma unroll
                    for (int j = 0; j < 4; j++) {
                        int r = rb + a * 16 + ((j >> 1) << 3);
                        int c = colL + (j & 1);
                        float v = tf32r(fmaxf(acc[a][b][j] + ((j & 1) ? bb1 : bb0), 0.f));
                        int rw = r & 15;
                        hb[(c >> 3) * AS + (r >> 4) * 128 + (rw & 7) * 16 + (rw >> 3)
                           + 2 * ((c >> 2) & 1) + 4 * (c & 3)] = v;
                    }
                }
            }
        }
        __syncthreads();

        // ---- stage 2: acc2 += h_half @ W2_half^T (all SMEM) ----
        #pragma unroll
        for (int kt2 = 0; kt2 < 4; kt2++) {
            #pragma unroll
            for (int ks = 0; ks < 4; ks++) {
                int g = kt2 * 4 + ks;
                uint32_t af[2][4], bf[4][2];
                #pragma unroll
                for (int a = 0; a < 2; a++)
                    *(float4*)af[a] = *(const float4*)(hb + g * AS
                                                       + (wm * 2 + a) * 128 + lane * 4);
                #pragma unroll
                for (int b = 0; b < 4; b++)
                    *(float2*)bf[b] = *(const float2*)(w2b + (h2 * 16 + g) * BS2
                                                       + (wn * 4 + b) * 64 + lane * 2);
                #pragma unroll
                for (int a = 0; a < 2; a++)
                    #pragma unroll
                    for (int b = 0; b < 4; b++) {
                        asm volatile(
                            "mma.sync.aligned.m16n8k8.row.col.f32.tf32.tf32.f32 "
                            "{%0,%1,%2,%3}, {%4,%5,%6,%7}, {%8,%9}, {%0,%1,%2,%3};"
                            : "+f"(acc2[a][b][0]), "+f"(acc2[a][b][1]),
                              "+f"(acc2[a][b][2]), "+f"(acc2[a][b][3])
                            : "r"(af[a][0]), "r"(af[a][1]), "r"(af[a][2]), "r"(af[a][3]),
                              "r"(bf[b][0]), "r"(bf[b][1]));
                    }
            }
        }
    }

    // ---- final store: logits cols < NCLS ----
    int rbase = m0 + wm * 32 + (lane >> 2);
    #pragma unroll
    for (int a = 0; a < 2; a++) {
        int r1 = rbase + a * 16;
        int r2 = r1 + 8;
        #pragma unroll
        for (int b = 0; b < 4; b++) {
            int col = wn * 32 + b * 8 + (lane & 3) * 2;
            if (col >= NCLS) continue;
            if (r1 < M) *(float2*)(C + (size_t)r1 * NPAD + col)
                      = make_float2(acc2[a][b][0], acc2[a][b][1]);
            if (r2 < M) *(float2*)(C + (size_t)r2 * NPAD + col)
                      = make_float2(acc2[a][b][2], acc2[a][b][3]);
        }
    }
}

// ---------------- layer-2 aggregation + bias + log_softmax -----------------
// one warp per node; 4x unrolled edge loop for MLP
__global__ void k_agg2_softmax(const float* __restrict__ b2,
                               float* __restrict__ out, int n) {
    int node = (blockIdx.x * blockDim.x + threadIdx.x) >> 5;
    int lane = threadIdx.x & 31;
    if (node >= n) return;
    int beg = g_rows[node];
    int cnt = g_cnt[node];
    float a0 = 0.f, a1 = 0.f;
    int i = 0;
    for (; i + 4 <= cnt; i += 4) {
        int s0 = g_csrc[beg + i + 0];
        int s1 = g_csrc[beg + i + 1];
        int s2 = g_csrc[beg + i + 2];
        int s3 = g_csrc[beg + i + 3];
        float w0 = g_dinv[s0], w1 = g_dinv[s1];
        float w2 = g_dinv[s2], w3 = g_dinv[s3];
        const float* r0 = g_l2h + (size_t)s0 * NPAD;
        const float* r1 = g_l2h + (size_t)s1 * NPAD;
        const float* r2 = g_l2h + (size_t)s2 * NPAD;
        const float* r3 = g_l2h + (size_t)s3 * NPAD;
        a0 += w0 * r0[lane] + w1 * r1[lane] + w2 * r2[lane] + w3 * r3[lane];
        if (lane < 8)
            a1 += w0 * r0[32 + lane] + w1 * r1[32 + lane]
                + w2 * r2[32 + lane] + w3 * r3[32 + lane];
    }
    for (; i < cnt; i++) {
        int s = g_csrc[beg + i];
        float ws = g_dinv[s];
        const float* row = g_l2h + (size_t)s * NPAD;
        a0 += ws * row[lane];
        if (lane < 8) a1 += ws * row[32 + lane];
    }
    float wd = g_dinv[node];
    const float* srow = g_l2h + (size_t)node * NPAD;
    float v0 = b2[lane] + wd * (a0 + wd * srow[lane]);
    float v1 = -1e30f;
    if (lane < 8) v1 = b2[32 + lane] + wd * (a1 + wd * srow[32 + lane]);

    float m = fmaxf(v0, v1);
    #pragma unroll
    for (int off = 16; off; off >>= 1)
        m = fmaxf(m, __shfl_xor_sync(0xffffffffu, m, off));
    float e = expf(v0 - m) + ((lane < 8) ? expf(v1 - m) : 0.f);
    #pragma unroll
    for (int off = 16; off; off >>= 1)
        e += __shfl_xor_sync(0xffffffffu, e, off);
    float lse = m + logf(e);

    out[(size_t)node * NCLS + lane] = v0 - lse;
    if (lane < 8) out[(size_t)node * NCLS + 32 + lane] = v1 - lse;
}

// ---------------- host ------------------------------------------------------
extern "C" void kernel_launch(void* const* d_in, const int* in_sizes, int n_in,
                              void* d_out, int out_size) {
    const float* x  = (const float*)d_in[0];
    const int*   ei = (const int*)d_in[1];
    const float* W1 = (const float*)d_in[2];
    const float* b1 = (const float*)d_in[3];
    const float* W2 = (const float*)d_in[4];
    const float* b2 = (const float*)d_in[5];
    float* out = (float*)d_out;

    int N = in_sizes[0] / F1;
    int E = in_sizes[1] / 2;
    const int* src = ei;
    const int* dst = ei + E;

    float *p_agg1, *p_l2h, *p_w1t, *p_w2t;
    int* p_cnt;
    cudaGetSymbolAddress((void**)&p_agg1, g_agg1);
    cudaGetSymbolAddress((void**)&p_l2h,  g_l2h);
    cudaGetSymbolAddress((void**)&p_w1t,  g_w1t);
    cudaGetSymbolAddress((void**)&p_w2t,  g_w2t);
    cudaGetSymbolAddress((void**)&p_cnt,  g_cnt);

    // fused-MLP dynamic SMEM: (4+16)*1032 + 4*1032 + 32*520 floats
    const int SMEMF = (24 * 1032 + 32 * 520) * 4;   // 165,632 B
    cudaFuncSetAttribute(k_fusedmlp,
                         cudaFuncAttributeMaxDynamicSharedMemorySize, SMEMF);

    int nb = (N + 1023) / 1024;
    int ntiles = (N + 127) / 128;

    cudaMemsetAsync(p_cnt, 0, (size_t)N * sizeof(int));
    k_count_wprep<<<(E + 255) / 256, 256>>>(dst, E, W1, W2);
    k_scan_assign<<<nb, 1024>>>(N);
    k_fill<<<(E + 255) / 256, 256>>>(src, dst, E);

    // layer 1 aggregate -> fused GEMM1+relu+GEMM2 (h1 never hits DRAM)
    k_agg1<<<((size_t)N * 32 + 255) / 256, 256>>>(x, N);
    k_fusedmlp<<<ntiles, 256, SMEMF>>>(p_agg1, p_w1t, b1, p_w2t, p_l2h, N);

    // aggregate logits + bias + log_softmax
    k_agg2_softmax<<<((size_t)N * 32 + 255) / 256, 256>>>(b2, out, N);
}

// round 13
// speedup vs baseline: 2.4106x; 1.4905x over previous
#include <cuda_runtime.h>
#include <cuda_fp16.h>
#include <cstdint>

// Problem constants (shapes fixed by the dataset).
#define NMAX   100000
#define EMAX   800000
#define F1     128      // input features
#define HID    256      // hidden
#define NCLS   40       // classes
#define NPAD   64       // padded classes

// ---------------- scratch (device globals; no allocation allowed) ----------
__device__ float  g_dinv[NMAX];
__device__ int    g_cnt[NMAX];
__device__ int    g_rows[NMAX];
__device__ int    g_cursor[NMAX];
__device__ int    g_csrc[EMAX];
__device__ int    g_total;
__device__ __half g_xh   [(size_t)NMAX * F1];   // 25.6 MB (x in fp16)
__device__ __half g_agg1h[(size_t)NMAX * F1];   // 25.6 MB (Â x, fp16)
__device__ __half g_l2hh [(size_t)NMAX * NPAD]; // 12.8 MB (logits, fp16)
__device__ __half g_w1h  [HID * F1];            // W1^T fp16
__device__ __half g_w2h  [NPAD * HID];          // W2^T padded fp16

// ---------------- prep: x->fp16 + degree count + weight prep ----------------
__global__ void k_prep(const float* __restrict__ x, int nx4,
                       const int* __restrict__ dst, int E,
                       const float* __restrict__ W1, const float* __restrict__ W2) {
    int t = blockIdx.x * blockDim.x + threadIdx.x;
    if (t == 0) g_total = 0;
    if (t < nx4) {
        float4 v = ((const float4*)x)[t];
        __half2 h0 = __floats2half2_rn(v.x, v.y);
        __half2 h1 = __floats2half2_rn(v.z, v.w);
        uint2 o;
        o.x = *(uint32_t*)&h0; o.y = *(uint32_t*)&h1;
        ((uint2*)g_xh)[t] = o;
    }
    if (t < E) atomicAdd(&g_cnt[dst[t]], 1);
    if (t < HID * F1) {
        int n = t / F1, k = t % F1;
        g_w1h[t] = __float2half_rn(W1[k * HID + n]);
    } else if (t < HID * F1 + NPAD * HID) {
        int u = t - HID * F1;
        int n = u / HID, k = u % HID;
        g_w2h[u] = __float2half_rn((n < NCLS) ? W2[k * NCLS + n] : 0.f);
    }
}

// ---------------- segment assignment: block scan + atomic base --------------
__global__ void k_scan_assign(int n) {
    __shared__ int s[1024];
    __shared__ int base;
    int t = threadIdx.x;
    int i = blockIdx.x * 1024 + t;
    int c = (i < n) ? g_cnt[i] : 0;
    s[t] = c;
    __syncthreads();
    #pragma unroll
    for (int off = 1; off < 1024; off <<= 1) {
        int add = (t >= off) ? s[t - off] : 0;
        __syncthreads();
        s[t] += add;
        __syncthreads();
    }
    int incl = s[t];
    if (t == 1023) base = atomicAdd(&g_total, s[1023]);
    __syncthreads();
    if (i < n) {
        int beg = base + incl - c;
        g_rows[i]   = beg;
        g_cursor[i] = beg;
        g_dinv[i]   = rsqrtf((float)(c + 1));
    }
}

__global__ void k_fill(const int* __restrict__ src, const int* __restrict__ dst, int E) {
    int e = blockIdx.x * blockDim.x + threadIdx.x;
    if (e < E) {
        int d = dst[e];
        int pos = atomicAdd(&g_cursor[d], 1);
        g_csrc[pos] = src[e];
    }
}

// ---------------- layer-1 aggregation: agg1 = Â x (fp16 gather) -------------
// one warp per node; lane holds 4 feats (uint2 = 4 halves); 4x unrolled
__global__ void k_agg1(int n) {
    int node = (blockIdx.x * blockDim.x + threadIdx.x) >> 5;
    int lane = threadIdx.x & 31;
    if (node >= n) return;
    int beg = g_rows[node];
    int cnt = g_cnt[node];
    const uint2* xv = (const uint2*)g_xh;
    float4 acc = make_float4(0.f, 0.f, 0.f, 0.f);
    int i = 0;
    for (; i + 4 <= cnt; i += 4) {
        int s0 = g_csrc[beg + i + 0];
        int s1 = g_csrc[beg + i + 1];
        int s2 = g_csrc[beg + i + 2];
        int s3 = g_csrc[beg + i + 3];
        float w0 = g_dinv[s0], w1 = g_dinv[s1];
        float w2 = g_dinv[s2], w3 = g_dinv[s3];
        uint2 u0 = xv[(size_t)s0 * 32 + lane];
        uint2 u1 = xv[(size_t)s1 * 32 + lane];
        uint2 u2 = xv[(size_t)s2 * 32 + lane];
        uint2 u3 = xv[(size_t)s3 * 32 + lane];
        float2 a = __half22float2(*(__half2*)&u0.x), b = __half22float2(*(__half2*)&u0.y);
        acc.x += w0 * a.x; acc.y += w0 * a.y; acc.z += w0 * b.x; acc.w += w0 * b.y;
        a = __half22float2(*(__half2*)&u1.x); b = __half22float2(*(__half2*)&u1.y);
        acc.x += w1 * a.x; acc.y += w1 * a.y; acc.z += w1 * b.x; acc.w += w1 * b.y;
        a = __half22float2(*(__half2*)&u2.x); b = __half22float2(*(__half2*)&u2.y);
        acc.x += w2 * a.x; acc.y += w2 * a.y; acc.z += w2 * b.x; acc.w += w2 * b.y;
        a = __half22float2(*(__half2*)&u3.x); b = __half22float2(*(__half2*)&u3.y);
        acc.x += w3 * a.x; acc.y += w3 * a.y; acc.z += w3 * b.x; acc.w += w3 * b.y;
    }
    for (; i < cnt; i++) {
        int s = g_csrc[beg + i];
        float ws = g_dinv[s];
        uint2 u = xv[(size_t)s * 32 + lane];
        float2 a = __half22float2(*(__half2*)&u.x), b = __half22float2(*(__half2*)&u.y);
        acc.x += ws * a.x; acc.y += ws * a.y; acc.z += ws * b.x; acc.w += ws * b.y;
    }
    float wd = g_dinv[node];
    uint2 us = xv[(size_t)node * 32 + lane];
    float2 sa = __half22float2(*(__half2*)&us.x), sb = __half22float2(*(__half2*)&us.y);
    __half2 o0 = __floats2half2_rn(wd * (acc.x + wd * sa.x), wd * (acc.y + wd * sa.y));
    __half2 o1 = __floats2half2_rn(wd * (acc.z + wd * sb.x), wd * (acc.w + wd * sb.y));
    uint2 o;
    o.x = *(uint32_t*)&o0; o.y = *(uint32_t*)&o1;
    ((uint2*)g_agg1h)[(size_t)node * 32 + lane] = o;
}

// ---------------- fused 2-layer MLP, fp16 m16n8k16 tensor cores -------------
// Per 128-row tile: whole A tile (128x128 fp16) staged once; per 128-hidden
// half: stage-1 mma -> relu/bias -> hb fragments -> stage-2 mma accumulate.
// All SMEM tiles stored in fragment-permuted order (LDS.128/LDS.64 loads).
__global__ void __launch_bounds__(256)
k_fusedmlp(const float* __restrict__ b1, __half* __restrict__ C, int M)
{
    constexpr int AS = 1028;   // uint32 words per k16 step (8 matoms x 128)
    constexpr int BS = 1028;   // stage-1 B (16 natoms x 64)
    constexpr int WS = 516;    // W2 fragments per step (8 natoms x 64)
    extern __shared__ uint32_t sm[];
    uint32_t* sA   = sm;              // 8*AS
    uint32_t* sB   = sA + 8 * AS;     // 8*BS
    uint32_t* hbuf = sB + 8 * BS;     // 8*AS (per-half reuse)
    uint32_t* w2b  = hbuf + 8 * AS;   // 16*WS

    int tid = threadIdx.x, lane = tid & 31, wid = tid >> 5;
    int wm = wid & 3, wn = wid >> 2;
    int m0 = blockIdx.x * 128;

    // ---- W2 fragments (once per CTA) ----
    const uint4* w2v = (const uint4*)g_w2h;        // [64 rows][32 uint4]
    for (int idx = tid; idx < 64 * 32; idx += 256) {
        int n = idx >> 5, q = idx & 31;
        uint4 v = w2v[idx];
        uint32_t* p = w2b + (q >> 1) * WS + (n >> 3) * 64 + (n & 7) * 8 + (q & 1);
        p[0] = v.x; p[2] = v.y; p[4] = v.z; p[6] = v.w;
    }

    // ---- A tile fragments (once per tile) ----
    const uint4* av = (const uint4*)g_agg1h;       // 16 uint4 per row
    #pragma unroll
    for (int it = 0; it < 8; it++) {
        int idx = it * 256 + tid;
        int r = idx >> 4, q = idx & 15;
        uint4 v = make_uint4(0u, 0u, 0u, 0u);
        if (m0 + r < M) v = av[(size_t)(m0 + r) * 16 + q];
        int rw = r & 15;
        uint32_t* p = sA + (q >> 1) * AS + (r >> 4) * 128 + (rw & 7) * 16
                    + (rw >> 3) + 2 * (q & 1);
        p[0] = v.x; p[4] = v.y; p[8] = v.z; p[12] = v.w;
    }

    float acc2[2][4][4];
    #pragma unroll
    for (int a = 0; a < 2; a++)
        #pragma unroll
        for (int b = 0; b < 4; b++)
            #pragma unroll
            for (int j = 0; j < 4; j++) acc2[a][b][j] = 0.f;

    #pragma unroll 1
    for (int h2 = 0; h2 < 2; h2++) {
        // ---- stage-1 B fragments: W1 half [128 n][128 k] ----
        const uint4* bv = (const uint4*)(g_w1h + (size_t)h2 * 128 * F1);
        #pragma unroll
        for (int it = 0; it < 8; it++) {
            int idx = it * 256 + tid;
            int n = idx >> 4, q = idx & 15;
            uint4 v = bv[idx];
            uint32_t* p = sB + (q >> 1) * BS + (n >> 3) * 64 + (n & 7) * 8 + (q & 1);
            p[0] = v.x; p[2] = v.y; p[4] = v.z; p[6] = v.w;
        }
        __syncthreads();

        // ---- stage 1: 8 k16 steps ----
        float acc[2][8][4];
        #pragma unroll
        for (int a = 0; a < 2; a++)
            #pragma unroll
            for (int b = 0; b < 8; b++)
                #pragma unroll
                for (int j = 0; j < 4; j++) acc[a][b][j] = 0.f;

        #pragma unroll
        for (int g = 0; g < 8; g++) {
            uint32_t af[2][4], bf[8][2];
            #pragma unroll
            for (int a = 0; a < 2; a++)
                *(uint4*)af[a] = *(const uint4*)(sA + g * AS + (wm * 2 + a) * 128
                                                 + lane * 4);
            #pragma unroll
            for (int b = 0; b < 8; b++)
                *(uint2*)bf[b] = *(const uint2*)(sB + g * BS + (wn * 8 + b) * 64
                                                 + lane * 2);
            #pragma unroll
            for (int a = 0; a < 2; a++)
                #pragma unroll
                for (int b = 0; b < 8; b++) {
                    asm volatile(
                        "mma.sync.aligned.m16n8k16.row.col.f32.f16.f16.f32 "
                        "{%0,%1,%2,%3}, {%4,%5,%6,%7}, {%8,%9}, {%0,%1,%2,%3};"
                        : "+f"(acc[a][b][0]), "+f"(acc[a][b][1]),
                          "+f"(acc[a][b][2]), "+f"(acc[a][b][3])
                        : "r"(af[a][0]), "r"(af[a][1]), "r"(af[a][2]), "r"(af[a][3]),
                          "r"(bf[b][0]), "r"(bf[b][1]));
                }
        }
        __syncthreads();   // sB consumed; hbuf free (prev half's stage 2 done)

        // ---- epilogue: bias+relu -> hbuf (stage-2 A fragments, fp16) ----
        {
            int rb = wm * 32 + (lane >> 2);
            #pragma unroll
            for (int a = 0; a < 2; a++) {
                #pragma unroll
                for (int b = 0; b < 8; b++) {
                    int cL = wn * 64 + b * 8 + (lane & 3) * 2;
                    float bb0 = __ldg(&b1[h2 * 128 + cL]);
                    float bb1 = __ldg(&b1[h2 * 128 + cL + 1]);
                    #pragma unroll
                    for (int jp = 0; jp < 2; jp++) {
                        int r = rb + a * 16 + jp * 8;
                        __half2 hv = __floats2half2_rn(
                            fmaxf(acc[a][b][jp * 2 + 0] + bb0, 0.f),
                            fmaxf(acc[a][b][jp * 2 + 1] + bb1, 0.f));
                        int rw = r & 15;
                        hbuf[(cL >> 4) * AS + (r >> 4) * 128 + (rw & 7) * 16
                             + 4 * ((cL & 7) >> 1) + (rw >> 3) + 2 * ((cL >> 3) & 1)]
                            = *(uint32_t*)&hv;
                    }
                }
            }
        }
        __syncthreads();

        // ---- stage 2: 8 k16 steps, acc2 += h_half @ W2_half^T ----
        #pragma unroll
        for (int gl = 0; gl < 8; gl++) {
            int gg = h2 * 8 + gl;
            uint32_t af[2][4], bf[4][2];
            #pragma unroll
            for (int a = 0; a < 2; a++)
                *(uint4*)af[a] = *(const uint4*)(hbuf + gl * AS + (wm * 2 + a) * 128
                                                 + lane * 4);
            #pragma unroll
            for (int b = 0; b < 4; b++)
                *(uint2*)bf[b] = *(const uint2*)(w2b + gg * WS + (wn * 4 + b) * 64
                                                 + lane * 2);
            #pragma unroll
            for (int a = 0; a < 2; a++)
                #pragma unroll
                for (int b = 0; b < 4; b++) {
                    asm volatile(
                        "mma.sync.aligned.m16n8k16.row.col.f32.f16.f16.f32 "
                        "{%0,%1,%2,%3}, {%4,%5,%6,%7}, {%8,%9}, {%0,%1,%2,%3};"
                        : "+f"(acc2[a][b][0]), "+f"(acc2[a][b][1]),
                          "+f"(acc2[a][b][2]), "+f"(acc2[a][b][3])
                        : "r"(af[a][0]), "r"(af[a][1]), "r"(af[a][2]), "r"(af[a][3]),
                          "r"(bf[b][0]), "r"(bf[b][1]));
                }
        }
        __syncthreads();   // hbuf consumed before next half overwrites
    }

    // ---- final store: logits cols < NCLS as fp16 ----
    int rbase = m0 + wm * 32 + (lane >> 2);
    #pragma unroll
    for (int a = 0; a < 2; a++) {
        #pragma unroll
        for (int b = 0; b < 4; b++) {
            int col = wn * 32 + b * 8 + (lane & 3) * 2;
            if (col >= NCLS) continue;
            #pragma unroll
            for (int jp = 0; jp < 2; jp++) {
                int r = rbase + a * 16 + jp * 8;
                if (r < M) {
                    __half2 hv = __floats2half2_rn(acc2[a][b][jp * 2 + 0],
                                                   acc2[a][b][jp * 2 + 1]);
                    ((__half2*)C)[(size_t)r * 32 + (col >> 1)] = hv;
                }
            }
        }
    }
}

// ---------------- layer-2 aggregation + bias + log_softmax -----------------
// one warp per node; lanes 0..19 each own class pair (2*lane, 2*lane+1)
__global__ void k_agg2_softmax(const float* __restrict__ b2,
                               float* __restrict__ out, int n) {
    int node = (blockIdx.x * blockDim.x + threadIdx.x) >> 5;
    int lane = threadIdx.x & 31;
    if (node >= n) return;
    bool act = lane < 20;
    int cl = act ? lane : 19;          // clamped addressing, no divergence
    int beg = g_rows[node];
    int cnt = g_cnt[node];
    const __half2* L = (const __half2*)g_l2hh;   // 32 half2 per row
    float a0 = 0.f, a1 = 0.f;
    int i = 0;
    for (; i + 4 <= cnt; i += 4) {
        int s0 = g_csrc[beg + i + 0];
        int s1 = g_csrc[beg + i + 1];
        int s2 = g_csrc[beg + i + 2];
        int s3 = g_csrc[beg + i + 3];
        float w0 = g_dinv[s0], w1 = g_dinv[s1];
        float w2 = g_dinv[s2], w3 = g_dinv[s3];
        float2 f0 = __half22float2(L[(size_t)s0 * 32 + cl]);
        float2 f1 = __half22float2(L[(size_t)s1 * 32 + cl]);
        float2 f2 = __half22float2(L[(size_t)s2 * 32 + cl]);
        float2 f3 = __half22float2(L[(size_t)s3 * 32 + cl]);
        a0 += w0 * f0.x + w1 * f1.x + w2 * f2.x + w3 * f3.x;
        a1 += w0 * f0.y + w1 * f1.y + w2 * f2.y + w3 * f3.y;
    }
    for (; i < cnt; i++) {
        int s = g_csrc[beg + i];
        float ws = g_dinv[s];
        float2 f = __half22float2(L[(size_t)s * 32 + cl]);
        a0 += ws * f.x; a1 += ws * f.y;
    }
    float wd = g_dinv[node];
    float2 fs = __half22float2(L[(size_t)node * 32 + cl]);
    float v0 = -1e30f, v1 = -1e30f;
    if (act) {
        v0 = b2[2 * lane]     + wd * (a0 + wd * fs.x);
        v1 = b2[2 * lane + 1] + wd * (a1 + wd * fs.y);
    }
    float m = fmaxf(v0, v1);
    #pragma unroll
    for (int off = 16; off; off >>= 1)
        m = fmaxf(m, __shfl_xor_sync(0xffffffffu, m, off));
    float e = expf(v0 - m) + expf(v1 - m);
    #pragma unroll
    for (int off = 16; off; off >>= 1)
        e += __shfl_xor_sync(0xffffffffu, e, off);
    float lse = m + logf(e);
    if (act)
        ((float2*)out)[(size_t)node * 20 + lane] = make_float2(v0 - lse, v1 - lse);
}

// ---------------- host ------------------------------------------------------
extern "C" void kernel_launch(void* const* d_in, const int* in_sizes, int n_in,
                              void* d_out, int out_size) {
    const float* x  = (const float*)d_in[0];
    const int*   ei = (const int*)d_in[1];
    const float* W1 = (const float*)d_in[2];
    const float* b1 = (const float*)d_in[3];
    const float* W2 = (const float*)d_in[4];
    const float* b2 = (const float*)d_in[5];
    float* out = (float*)d_out;

    int N = in_sizes[0] / F1;
    int E = in_sizes[1] / 2;
    const int* src = ei;
    const int* dst = ei + E;

    int* p_cnt;
    __half* p_l2hh;
    cudaGetSymbolAddress((void**)&p_cnt,  g_cnt);
    cudaGetSymbolAddress((void**)&p_l2hh, g_l2hh);

    // fused-MLP dynamic SMEM: (8+8+8)*1028 + 16*516 uint32 words
    const int SMEMF = (24 * 1028 + 16 * 516) * 4;   // 131,712 B
    cudaFuncSetAttribute(k_fusedmlp,
                         cudaFuncAttributeMaxDynamicSharedMemorySize, SMEMF);

    int nx4 = N * F1 / 4;                 // 3.2M half4 groups
    int nb = (N + 1023) / 1024;
    int ntiles = (N + 127) / 128;

    cudaMemsetAsync(p_cnt, 0, (size_t)N * sizeof(int));
    k_prep<<<(nx4 + 255) / 256, 256>>>(x, nx4, dst, E, W1, W2);
    k_scan_assign<<<nb, 1024>>>(N);
    k_fill<<<(E + 255) / 256, 256>>>(src, dst, E);

    // layer 1 aggregate (fp16 gather) -> fused fp16 GEMM1+relu+GEMM2
    k_agg1<<<((size_t)N * 32 + 255) / 256, 256>>>(N);
    k_fusedmlp<<<ntiles, 256, SMEMF>>>(b1, p_l2hh, N);

    // aggregate logits + bias + log_softmax
    k_agg2_softmax<<<((size_t)N * 32 + 255) / 256, 256>>>(b2, out, N);
}